// round 15
// baseline (speedup 1.0000x reference)
#include <cuda_runtime.h>
#include <cuda_fp16.h>
#include <cstdint>

#define BB 64
#define HH 256
#define WW 256
#define TH 64                      // output rows per mapK tile
#define NT 256
#define ARMAX (TH + 10)            // 74 bits-rows incl R=5 halo
#define SBW 10                     // padded bits row: zero word each side of 8

typedef unsigned long long ull;

__device__ __align__(16) uint32_t g_bits[3][BB][HH][8];        // 1 bit/px masks
__device__ __align__(16) uint32_t g_maph[3][BB][HH * WW / 2];  // fp16x2 unnormalized maps
__device__ float g_max[3 * BB];    // zero-init; atomicMax idempotent across replays

__device__ __forceinline__ int map_ch(int m) { return (m == 0) ? 2 : (m == 1) ? 1 : 3; }

// ---- packed f32x2 helpers (sm_103a) ----
__device__ __forceinline__ ull f2pack(uint32_t lo, uint32_t hi) {
    ull r; asm("mov.b64 %0, {%1, %2};" : "=l"(r) : "r"(lo), "r"(hi)); return r;
}
__device__ __forceinline__ void f2unpack(ull v, float& lo, float& hi) {
    asm("mov.b64 {%0, %1}, %2;" : "=f"(lo), "=f"(hi) : "l"(v));
}
__device__ __forceinline__ ull f2add(ull a, ull b) {
    ull r; asm("add.rn.f32x2 %0, %1, %2;" : "=l"(r) : "l"(a), "l"(b)); return r;
}
__device__ __forceinline__ ull f2mul(ull a, ull b) {
    ull r; asm("mul.rn.f32x2 %0, %1, %2;" : "=l"(r) : "l"(a), "l"(b)); return r;
}
__device__ __forceinline__ ull f2fma(ull a, ull b, ull c) {
    ull r; asm("fma.rn.f32x2 %0, %1, %2, %3;" : "=l"(r) : "l"(a), "l"(b), "l"(c)); return r;
}

// ============ Kernel 1: threshold channels into bit array (bits only) ============
__global__ void __launch_bounds__(NT) bitK(const float* __restrict__ x) {
    const int b = blockIdx.y;
    const int m = blockIdx.z;
    const size_t plane = (size_t)HH * WW;

    const float* src = x + ((size_t)b * 4 + map_ch(m)) * plane;
    const int warp = threadIdx.x >> 5;
    const int lane = threadIdx.x & 31;
    const int r0 = blockIdx.x * 32 + warp * 4;

#pragma unroll
    for (int rr = 0; rr < 4; rr++) {
        const int r = r0 + rr;
        const float* rp = src + (size_t)r * WW;
        float v[8];
#pragma unroll
        for (int k = 0; k < 8; k++) v[k] = rp[32 * k + lane];
        uint32_t mine = 0;
#pragma unroll
        for (int k = 0; k < 8; k++) {
            uint32_t w = __ballot_sync(0xFFFFFFFFu, v[k] > 0.f);
            if (lane == k) mine = w;
        }
        if (lane < 8) g_bits[m][b][r][lane] = mine;
    }
}

// ============ LUT build: LUT[i] = sum over set bits p of wg[|p - R|] ============
template <int R>
__device__ __forceinline__ void buildLUT(const float* wg, float* LUT) {
    if constexpr (R == 5) {
        const int t = threadIdx.x;           // entry i = t*8 + j; bits 3..10 from t
        float base = 0.f;
#pragma unroll
        for (int b = 0; b < 8; b++) {
            int pos = b + 3;
            int ai = (pos < 5) ? (5 - pos) : (pos - 5);
            if ((t >> b) & 1) base += wg[ai];
        }
        float comb[8];
        comb[0] = 0.f;           comb[1] = wg[5];
        comb[2] = wg[4];         comb[3] = wg[5] + wg[4];
        comb[4] = wg[3];         comb[5] = wg[3] + wg[5];
        comb[6] = wg[3] + wg[4]; comb[7] = wg[3] + wg[4] + wg[5];
#pragma unroll
        for (int j = 0; j < 8; j++) LUT[t * 8 + j] = base + comb[j];
    } else {
        if (threadIdx.x < 32) {
            const int i = threadIdx.x;
            float s = 0.f;
#pragma unroll
            for (int b = 0; b < 5; b++) {
                int ai = (b < 2) ? (2 - b) : (b - 2);
                if ((i >> b) & 1) s += wg[ai];
            }
            LUT[i] = s;
        }
    }
}

// ============ Kernel 2: single-pass conv from bits (+ ch0 copy slice) ============
template <int R, int M>
__device__ __forceinline__ void runMap(int b, float i2s, int row0,
                                       float* LUT, uint32_t (*Sb)[SBW], float* red) {
    constexpr int W = 2 * R + 1;
    constexpr int AR = TH + 2 * R;

    float wg[R + 1];
#pragma unroll
    for (int d = 0; d <= R; d++) wg[d] = __expf(-(float)(d * d) * i2s);

    buildLUT<R>(wg, LUT);

    for (int idx = threadIdx.x; idx < AR * 8; idx += NT) {
        const int r = idx >> 3, w = idx & 7;
        const int gr = row0 - R + r;
        Sb[r][w + 1] = ((unsigned)gr < HH) ? g_bits[M][b][gr][w] : 0u;
    }
    for (int idx = threadIdx.x; idx < AR * 2; idx += NT)
        Sb[idx >> 1][(idx & 1) ? 9 : 0] = 0u;
    __syncthreads();

    ull w2[R + 1];
#pragma unroll
    for (int d = 0; d <= R; d++)
        w2[d] = f2pack(__float_as_uint(wg[d]), __float_as_uint(wg[d]));

    const int jc = (threadIdx.x & 127) * 2;   // column pair
    const int t0 = (threadIdx.x >> 7) * 32;   // row group

    const int bitpos = jc + 32 - R;
    const int wi = bitpos >> 5;
    const unsigned sh = bitpos & 31u;
    const uint32_t msk = (1u << W) - 1u;

    ull win[W];
#pragma unroll
    for (int k = 0; k < W; k++) {
        uint32_t v = __funnelshift_r(Sb[t0 + k][wi], Sb[t0 + k][wi + 1], sh);
        win[k] = f2pack(__float_as_uint(LUT[v & msk]),
                        __float_as_uint(LUT[(v >> 1) & msk]));
    }

    uint32_t* gdst = g_maph[M][b];
    float mx = 0.f;
#pragma unroll
    for (int t = 0; t < 32; t++) {
        ull acc = f2mul(w2[0], win[R]);
#pragma unroll
        for (int d = 1; d <= R; d++)
            acc = f2fma(w2[d], f2add(win[R - d], win[R + d]), acc);
        float lo, hi; f2unpack(acc, lo, hi);
        uint32_t h2;
        asm("cvt.rn.f16x2.f32 %0, %1, %2;" : "=r"(h2) : "f"(hi), "f"(lo));
        gdst[(size_t)(row0 + t0 + t) * (WW / 2) + (jc >> 1)] = h2;
        mx = fmaxf(mx, fmaxf(lo, hi));
#pragma unroll
        for (int k = 0; k < W - 1; k++) win[k] = win[k + 1];
        if (t < 31) {
            uint32_t v = __funnelshift_r(Sb[t0 + t + W][wi], Sb[t0 + t + W][wi + 1], sh);
            win[W - 1] = f2pack(__float_as_uint(LUT[v & msk]),
                                __float_as_uint(LUT[(v >> 1) & msk]));
        }
    }

    // block max -> one atomic (values >= 0; int compare order-preserving)
#pragma unroll
    for (int o = 16; o; o >>= 1)
        mx = fmaxf(mx, __shfl_xor_sync(0xFFFFFFFFu, mx, o));
    if ((threadIdx.x & 31) == 0) red[threadIdx.x >> 5] = mx;
    __syncthreads();
    if (threadIdx.x < 8) {
        float v = red[threadIdx.x];
#pragma unroll
        for (int o = 4; o; o >>= 1)
            v = fmaxf(v, __shfl_xor_sync(0xFFu, v, o));
        if (threadIdx.x == 0)
            atomicMax((int*)&g_max[M * BB + b], __float_as_int(v));
    }
}

__global__ void __launch_bounds__(NT) mapK(const float* __restrict__ x,
                                           float* __restrict__ out) {
    __shared__ float LUT[2048];
    __shared__ uint32_t Sb[ARMAX][SBW];
    __shared__ float red[8];

    const int row0 = blockIdx.x * TH;
    const int b = blockIdx.y;
    const int m = blockIdx.z;
    const size_t plane = (size_t)HH * WW;

    if (m == 3) {     // ch0 passthrough — pure-DRAM blocks overlap LDS-bound map blocks
        const size_t off = (size_t)blockIdx.x * 16384;
        const float4* s = (const float4*)(x + (size_t)b * 4 * plane + off);
        float4* d = (float4*)(out + (size_t)b * 5 * plane + off);
#pragma unroll
        for (int k = 0; k < 16; k++)
            d[threadIdx.x + 256 * k] = s[threadIdx.x + 256 * k];
        return;
    }

    if (m == 2)
        runMap<2, 2>(b, 2.0f, row0, LUT, Sb, red);   // hist,   sigma=0.5
    else if (m == 1)
        runMap<5, 1>(b, 0.5f, row0, LUT, Sb, red);   // cost,   sigma=1
    else
        runMap<5, 0>(b, 0.5f, row0, LUT, Sb, red);   // target, sigma=1
}

// ============ Kernel 3: normalize + write, one output channel per z-slice ============
__global__ void __launch_bounds__(256) finK(float* __restrict__ out) {
    const int b = blockIdx.y;
    const int z = blockIdx.z;                 // 0=target,1=cost,2=hist,3=mul
    const size_t px = ((size_t)blockIdx.x << 10) | ((size_t)threadIdx.x << 2);
    const size_t plane = (size_t)HH * WW;
    float* ob = out + (size_t)b * 5 * plane;

    if (z < 3) {
        float s = g_max[z * BB + b]; s = 1.0f / ((s == 0.f) ? 1.f : s);
        uint2 w = *(const uint2*)(&g_maph[z][b][px >> 1]);
        float2 a = __half22float2(*(__half2*)&w.x);
        float2 c = __half22float2(*(__half2*)&w.y);
        *(float4*)(ob + (size_t)(z + 1) * plane + px) =
            make_float4(a.x * s, a.y * s, c.x * s, c.y * s);
    } else {
        float st = g_max[b];      st = 1.0f / ((st == 0.f) ? 1.f : st);
        float sc = g_max[BB + b]; sc = 1.0f / ((sc == 0.f) ? 1.f : sc);
        uint2 tw = *(const uint2*)(&g_maph[0][b][px >> 1]);
        uint2 cw = *(const uint2*)(&g_maph[1][b][px >> 1]);
        float2 ta = __half22float2(*(__half2*)&tw.x), tb = __half22float2(*(__half2*)&tw.y);
        float2 ca = __half22float2(*(__half2*)&cw.x), cb = __half22float2(*(__half2*)&cw.y);
        *(float4*)(ob + 4 * plane + px) =
            make_float4(ta.x * st * ca.x * sc, ta.y * st * ca.y * sc,
                        tb.x * st * cb.x * sc, tb.y * st * cb.y * sc);
    }
}

extern "C" void kernel_launch(void* const* d_in, const int* in_sizes, int n_in,
                              void* d_out, int out_size) {
    const float* x = (const float*)d_in[0];
    float* out = (float*)d_out;

    bitK<<<dim3(8, BB, 3), NT>>>(x);
    mapK<<<dim3(HH / TH, BB, 4), NT>>>(x, out);
    finK<<<dim3(64, BB, 4), 256>>>(out);
}